// round 6
// baseline (speedup 1.0000x reference)
#include <cuda_runtime.h>
#include <cuda_fp16.h>
#include <mma.h>
#include <cstdint>
using namespace nvcuda;

// Problem dims (fixed)
#define BB   1024
#define TT   128
#define DD   128
#define HH   8
#define HDIM 16
#define FFD  512
#define NL   2
#define MM   (BB*TT)          // 131072 tokens

// fp16 scratch (device globals: allocation-free per harness rules)
__device__ __half g_wqkv[(size_t)NL * 3 * DD * DD];
__device__ __half g_wout[(size_t)NL * DD * DD];
__device__ __half g_wff1[(size_t)NL * FFD * DD];
__device__ __half g_wff2[(size_t)NL * DD * FFD];
__device__ __half g_xh  [(size_t)MM * DD];        // fp16 mirror of x
__device__ __half g_qkvh[(size_t)MM * 3 * DD];
__device__ __half g_attnh[(size_t)MM * DD];
__device__ __half g_hh  [(size_t)MM * FFD];

// ---------------------------------------------------------------------------
__global__ void cvt_f2h(const float* __restrict__ src, __half* __restrict__ dst, int n4) {
    int i = blockIdx.x * blockDim.x + threadIdx.x;
    if (i < n4) {
        float4 v = ((const float4*)src)[i];
        __half2 h0 = __floats2half2_rn(v.x, v.y);
        __half2 h1 = __floats2half2_rn(v.z, v.w);
        uint2 u;
        u.x = *reinterpret_cast<uint32_t*>(&h0);
        u.y = *reinterpret_cast<uint32_t*>(&h1);
        ((uint2*)dst)[i] = u;
    }
}

// ---------------------------------------------------------------------------
// fp16 tensor GEMM: C[M,N] = A[M,K] @ W[N,K]^T + bias.
// mode 0: fp16 out   mode 1: ReLU fp16 out
// mode 2: fused residual+LN (N==128): X <- LN(X + gemm + bias)*gamma+beta + Xh mirror
// Tile 128x128, BK=32, 4-stage cp.async, 128 threads (4 warps x 64x64),
// one __syncthreads per K-iter, 2 CTAs/SM.
// ---------------------------------------------------------------------------
#define BK   32
#define ALD  40                          // halves per smem row (32+8 pad)
#define STG_B 20480                      // bytes/stage: A 10240 + W 10240
#define NS   4
#define CLD  132
#define SMEM_DYN (NS*STG_B)              // 81920 B

__device__ __forceinline__ uint32_t smem_u32(const void* p) {
    uint32_t a;
    asm("{ .reg .u64 t; cvta.to.shared.u64 t, %1; cvt.u32.u64 %0, t; }"
        : "=r"(a) : "l"(p));
    return a;
}
__device__ __forceinline__ void cp16(uint32_t dst, const void* src) {
    asm volatile("cp.async.ca.shared.global [%0], [%1], 16;" :: "r"(dst), "l"(src));
}

__global__ __launch_bounds__(128, 2) void gemm_h(
    const __half* __restrict__ A, const __half* __restrict__ W,
    const float* __restrict__ bias,
    __half* __restrict__ Ch,                       // modes 0/1
    float* __restrict__ X, __half* __restrict__ Xh,// mode 2
    const float* __restrict__ gamma, const float* __restrict__ beta,
    int N, int K, int mode)
{
    extern __shared__ __align__(16) char smem[];
    const uint32_t sbase = smem_u32(smem);
    const int tid  = threadIdx.x;
    const int wid  = tid >> 5;
    const int lane = tid & 31;
    const int wm   = wid & 1;            // 64-row group
    const int wn   = wid >> 1;           // 64-col group
    const size_t bm = (size_t)blockIdx.y * 128;
    const size_t bn = (size_t)blockIdx.x * 128;
    const int NT = K / BK;

    const int lr = tid >> 2;             // 0..31
    const int lc = tid & 3;              // 16B chunk in row

    wmma::fragment<wmma::accumulator, 16, 16, 16, float> acc[4][4];
#pragma unroll
    for (int i = 0; i < 4; i++)
#pragma unroll
        for (int j = 0; j < 4; j++) wmma::fill_fragment(acc[i][j], 0.f);

    // prologue: issue NS-1 stages
#pragma unroll
    for (int t = 0; t < NS - 1; t++) {
        if (t < NT) {
            const int kk = t * BK;
            const uint32_t sb = sbase + (t % NS) * STG_B;
#pragma unroll
            for (int p = 0; p < 4; p++) {
                const int row = lr + p * 32;
                cp16(sb + (row * ALD + lc * 8) * 2, A + (bm + row) * K + kk + lc * 8);
                cp16(sb + 10240 + (row * ALD + lc * 8) * 2, W + (bn + row) * K + kk + lc * 8);
            }
        }
        asm volatile("cp.async.commit_group;");
    }

    for (int t = 0; t < NT; t++) {
        asm volatile("cp.async.wait_group %0;" :: "n"(NS - 2));
        __syncthreads();
        // issue stage t+NS-1 (writes buffer whose readers finished at iter t-1)
        {
            const int tn = t + NS - 1;
            if (tn < NT) {
                const int kk = tn * BK;
                const uint32_t sb = sbase + (tn % NS) * STG_B;
#pragma unroll
                for (int p = 0; p < 4; p++) {
                    const int row = lr + p * 32;
                    cp16(sb + (row * ALD + lc * 8) * 2, A + (bm + row) * K + kk + lc * 8);
                    cp16(sb + 10240 + (row * ALD + lc * 8) * 2, W + (bn + row) * K + kk + lc * 8);
                }
            }
            asm volatile("cp.async.commit_group;");
        }
        // compute tile t
        {
            const __half* As = (const __half*)(smem + (t % NS) * STG_B);
            const __half* Ws = As + 5120;
#pragma unroll
            for (int ks = 0; ks < 2; ks++) {
                wmma::fragment<wmma::matrix_a, 16, 16, 16, __half, wmma::row_major> af[4];
                wmma::fragment<wmma::matrix_b, 16, 16, 16, __half, wmma::col_major> bf[4];
#pragma unroll
                for (int i = 0; i < 4; i++)
                    wmma::load_matrix_sync(af[i], As + (wm * 64 + i * 16) * ALD + ks * 16, ALD);
#pragma unroll
                for (int j = 0; j < 4; j++)
                    wmma::load_matrix_sync(bf[j], Ws + (wn * 64 + j * 16) * ALD + ks * 16, ALD);
#pragma unroll
                for (int i = 0; i < 4; i++)
#pragma unroll
                    for (int j = 0; j < 4; j++)
                        wmma::mma_sync(acc[i][j], af[i], bf[j], acc[i][j]);
            }
        }
    }
    __syncthreads();   // all warps done with pipeline buffers before epilogue staging

    // Epilogue: stage f32 accumulators in smem
    float* smf = (float*)smem;
#pragma unroll
    for (int i = 0; i < 4; i++)
#pragma unroll
        for (int j = 0; j < 4; j++)
            wmma::store_matrix_sync(smf + (wm * 64 + i * 16) * CLD + wn * 64 + j * 16,
                                    acc[i][j], CLD, wmma::mem_row_major);
    __syncthreads();

    if (mode == 2) {
        // fused residual + LayerNorm (N==128, bn==0); warp per row, 32 rows/warp
        float4 gv = *(const float4*)(gamma + lane * 4);
        float4 bv = *(const float4*)(beta  + lane * 4);
        float4 bz = *(const float4*)(bias  + lane * 4);
#pragma unroll
        for (int i = 0; i < 32; i++) {
            const int row = wid * 32 + i;
            float4 v = *(float4*)(smf + row * CLD + lane * 4);
            const size_t off = (bm + row) * DD + lane * 4;
            float4 xv = *(const float4*)(X + off);
            float4 tv;
            tv.x = v.x + bz.x + xv.x; tv.y = v.y + bz.y + xv.y;
            tv.z = v.z + bz.z + xv.z; tv.w = v.w + bz.w + xv.w;
            float s  = tv.x + tv.y + tv.z + tv.w;
            float s2 = tv.x*tv.x + tv.y*tv.y + tv.z*tv.z + tv.w*tv.w;
#pragma unroll
            for (int o = 16; o > 0; o >>= 1) {
                s  += __shfl_xor_sync(0xffffffffu, s,  o);
                s2 += __shfl_xor_sync(0xffffffffu, s2, o);
            }
            float mean = s * (1.f / DD);
            float var  = s2 * (1.f / DD) - mean * mean;
            float rstd = rsqrtf(var + 1e-5f);
            float4 y;
            y.x = (tv.x - mean) * rstd * gv.x + bv.x;
            y.y = (tv.y - mean) * rstd * gv.y + bv.y;
            y.z = (tv.z - mean) * rstd * gv.z + bv.z;
            y.w = (tv.w - mean) * rstd * gv.w + bv.w;
            *(float4*)(X + off) = y;
            __half2 h0 = __floats2half2_rn(y.x, y.y);
            __half2 h1 = __floats2half2_rn(y.z, y.w);
            uint2 u;
            u.x = *reinterpret_cast<uint32_t*>(&h0);
            u.y = *reinterpret_cast<uint32_t*>(&h1);
            *(uint2*)(Xh + off) = u;
        }
    } else {
        // bias (+ReLU), fp16 out: 4096 float4 reads, 32/thread
#pragma unroll
        for (int i = 0; i < 32; i++) {
            int idx = i * 128 + tid;
            int row = idx >> 5;
            int cc  = (idx & 31) * 4;
            float4 v  = *(float4*)(smf + row * CLD + cc);
            float4 bz = *(const float4*)(bias + bn + cc);
            v.x += bz.x; v.y += bz.y; v.z += bz.z; v.w += bz.w;
            if (mode == 1) {
                v.x = fmaxf(v.x, 0.f); v.y = fmaxf(v.y, 0.f);
                v.z = fmaxf(v.z, 0.f); v.w = fmaxf(v.w, 0.f);
            }
            __half2 h0 = __floats2half2_rn(v.x, v.y);
            __half2 h1 = __floats2half2_rn(v.z, v.w);
            uint2 u;
            u.x = *reinterpret_cast<uint32_t*>(&h0);
            u.y = *reinterpret_cast<uint32_t*>(&h1);
            *(uint2*)(Ch + (bm + row) * N + bn + cc) = u;
        }
    }
}

// ---------------------------------------------------------------------------
// Fast exp (FFMA-only)
// ---------------------------------------------------------------------------
__device__ __forceinline__ float fast_exp(float x) {
    x = fmaxf(x, -80.f);
    float t  = x * 1.4426950408889634f;
    float fn = t + 12582912.f;
    int   ni = __float_as_int(fn) - 0x4B400000;
    float r  = t - (fn - 12582912.f);
    float p  = 0.00133336f;
    p = fmaf(p, r, 0.00961813f);
    p = fmaf(p, r, 0.05550411f);
    p = fmaf(p, r, 0.24022651f);
    p = fmaf(p, r, 0.69314718f);
    p = fmaf(p, r, 1.0f);
    return p * __int_as_float((ni + 127) << 23);
}

// ---------------------------------------------------------------------------
// Attention: fp16 qkv in, fp16 out; fp32 math. One block per (b,h).
// ---------------------------------------------------------------------------
__global__ __launch_bounds__(128) void attn_kernel(
    const __half* __restrict__ qkv, const float* __restrict__ mask,
    __half* __restrict__ out)
{
    const int h = blockIdx.x;
    const int b = blockIdx.y;
    const int t = threadIdx.x;

    __shared__ float ks[TT][HDIM];
    __shared__ float vs[TT][HDIM];
    __shared__ float ms[TT];

    const __half* base = qkv + (size_t)b * TT * 3 * DD;
    {
        const __half* kr = base + (size_t)t * 3 * DD + DD + h * HDIM;
        const __half* vr = kr + DD;
#pragma unroll
        for (int c = 0; c < 2; c++) {
            uint4 rk = ((const uint4*)kr)[c];
            uint4 rv = ((const uint4*)vr)[c];
            const uint32_t* pk = &rk.x;
            const uint32_t* pv = &rv.x;
#pragma unroll
            for (int j = 0; j < 4; j++) {
                float2 fk = __half22float2(*(const __half2*)&pk[j]);
                float2 fv = __half22float2(*(const __half2*)&pv[j]);
                ks[t][c * 8 + j * 2]     = fk.x;
                ks[t][c * 8 + j * 2 + 1] = fk.y;
                vs[t][c * 8 + j * 2]     = fv.x;
                vs[t][c * 8 + j * 2 + 1] = fv.y;
            }
        }
        ms[t] = mask[b * TT + t];
    }
    __syncthreads();

    float q[HDIM];
    {
        const __half* qr = base + (size_t)t * 3 * DD + h * HDIM;
#pragma unroll
        for (int c = 0; c < 2; c++) {
            uint4 rq = ((const uint4*)qr)[c];
            const uint32_t* pq = &rq.x;
#pragma unroll
            for (int j = 0; j < 4; j++) {
                float2 fq = __half22float2(*(const __half2*)&pq[j]);
                q[c * 8 + j * 2]     = fq.x;
                q[c * 8 + j * 2 + 1] = fq.y;
            }
        }
    }

    const float scale = 0.25f;
    float s = 0.f;
    float o[HDIM];
#pragma unroll
    for (int c = 0; c < HDIM; c++) o[c] = 0.f;

    for (int j = 0; j < TT; j++) {
        float d = 0.f;
#pragma unroll
        for (int c = 0; c < HDIM; c++) d = fmaf(q[c], ks[j][c], d);
        float p = fast_exp(fmaf(d, scale, ms[j]));
        s += p;
#pragma unroll
        for (int c = 0; c < HDIM; c++) o[c] = fmaf(p, vs[j][c], o[c]);
    }
    float inv = 1.f / s;
    __half* op = out + (size_t)(b * TT + t) * DD + h * HDIM;
    uint4 w[2];
#pragma unroll
    for (int c = 0; c < 2; c++) {
        uint32_t* pw = &w[c].x;
#pragma unroll
        for (int j = 0; j < 4; j++) {
            __half2 hv = __floats2half2_rn(o[c * 8 + j * 2] * inv,
                                           o[c * 8 + j * 2 + 1] * inv);
            pw[j] = *reinterpret_cast<uint32_t*>(&hv);
        }
        ((uint4*)op)[c] = w[c];
    }
}

// ---------------------------------------------------------------------------
extern "C" void kernel_launch(void* const* d_in, const int* in_sizes, int n_in,
                              void* d_out, int out_size)
{
    const float* x_in      = (const float*)d_in[0];
    const float* mask      = (const float*)d_in[1];
    const float* in_proj_w = (const float*)d_in[2];
    const float* in_proj_b = (const float*)d_in[3];
    const float* out_w     = (const float*)d_in[4];
    const float* out_b     = (const float*)d_in[5];
    const float* ln1_g     = (const float*)d_in[6];
    const float* ln1_b     = (const float*)d_in[7];
    const float* ff1_w     = (const float*)d_in[8];
    const float* ff1_b     = (const float*)d_in[9];
    const float* ff2_w     = (const float*)d_in[10];
    const float* ff2_b     = (const float*)d_in[11];
    const float* ln2_g     = (const float*)d_in[12];
    const float* ln2_b     = (const float*)d_in[13];
    float* x = (float*)d_out;

    __half *wqkv, *wout, *wff1, *wff2, *xh, *qkvh, *attnh, *hh;
    cudaGetSymbolAddress((void**)&wqkv, g_wqkv);
    cudaGetSymbolAddress((void**)&wout, g_wout);
    cudaGetSymbolAddress((void**)&wff1, g_wff1);
    cudaGetSymbolAddress((void**)&wff2, g_wff2);
    cudaGetSymbolAddress((void**)&xh,   g_xh);
    cudaGetSymbolAddress((void**)&qkvh, g_qkvh);
    cudaGetSymbolAddress((void**)&attnh,g_attnh);
    cudaGetSymbolAddress((void**)&hh,   g_hh);

    cudaFuncSetAttribute(gemm_h, cudaFuncAttributeMaxDynamicSharedMemorySize, SMEM_DYN);

    cudaMemcpyAsync(x, x_in, sizeof(float) * (size_t)MM * DD,
                    cudaMemcpyDeviceToDevice);
    {
        int n;
        n = NL * 3 * DD * DD / 4; cvt_f2h<<<(n + 255) / 256, 256>>>(in_proj_w, wqkv, n);
        n = NL * DD * DD / 4;     cvt_f2h<<<(n + 255) / 256, 256>>>(out_w,  wout, n);
        n = NL * FFD * DD / 4;    cvt_f2h<<<(n + 255) / 256, 256>>>(ff1_w,  wff1, n);
        n = NL * DD * FFD / 4;    cvt_f2h<<<(n + 255) / 256, 256>>>(ff2_w,  wff2, n);
        n = MM * DD / 4;          cvt_f2h<<<(n + 255) / 256, 256>>>(x_in,   xh,   n);
    }

    for (int l = 0; l < NL; l++) {
        // qkv = x @ Wqkv^T + b   [MM, 384] fp16
        gemm_h<<<dim3(3, MM / 128), 128, SMEM_DYN>>>(
            xh, wqkv + (size_t)l * 3 * DD * DD, in_proj_b + (size_t)l * 3 * DD,
            qkvh, nullptr, nullptr, nullptr, nullptr, 3 * DD, DD, 0);
        // attention -> attnh [MM, DD] fp16
        attn_kernel<<<dim3(HH, BB), 128>>>(qkvh, mask, attnh);
        // x = LN(x + attnh @ out_w^T + out_b); xh mirror
        gemm_h<<<dim3(1, MM / 128), 128, SMEM_DYN>>>(
            attnh, wout + (size_t)l * DD * DD, out_b + (size_t)l * DD,
            nullptr, x, xh, ln1_g + (size_t)l * DD, ln1_b + (size_t)l * DD, DD, DD, 2);
        // h = relu(x @ ff1_w^T + b) -> hh [MM, FFD] fp16
        gemm_h<<<dim3(4, MM / 128), 128, SMEM_DYN>>>(
            xh, wff1 + (size_t)l * FFD * DD, ff1_b + (size_t)l * FFD,
            hh, nullptr, nullptr, nullptr, nullptr, FFD, DD, 1);
        // x = LN(x + hh @ ff2_w^T + b); xh mirror
        gemm_h<<<dim3(1, MM / 128), 128, SMEM_DYN>>>(
            hh, wff2 + (size_t)l * DD * FFD, ff2_b + (size_t)l * DD,
            nullptr, x, xh, ln2_g + (size_t)l * DD, ln2_b + (size_t)l * DD, DD, FFD, 2);
    }
}

// round 7
// speedup vs baseline: 1.0652x; 1.0652x over previous
#include <cuda_runtime.h>
#include <cuda_fp16.h>
#include <mma.h>
#include <cstdint>
using namespace nvcuda;

// Problem dims (fixed)
#define BB   1024
#define TT   128
#define DD   128
#define HH   8
#define HDIM 16
#define FFD  512
#define NL   2
#define MM   (BB*TT)          // 131072 tokens

// fp16 scratch (device globals: allocation-free per harness rules)
__device__ __half g_wqkv[(size_t)NL * 3 * DD * DD];
__device__ __half g_wout[(size_t)NL * DD * DD];
__device__ __half g_wff1[(size_t)NL * FFD * DD];
__device__ __half g_wff2[(size_t)NL * DD * FFD];
__device__ __half g_xh  [(size_t)MM * DD];        // fp16 mirror of x
__device__ __half g_qkvh[(size_t)MM * 3 * DD];
__device__ __half g_attnh[(size_t)MM * DD];
__device__ __half g_hh  [(size_t)MM * FFD];

// ---------------------------------------------------------------------------
__global__ void cvt_f2h(const float* __restrict__ src, __half* __restrict__ dst, int n4) {
    int i = blockIdx.x * blockDim.x + threadIdx.x;
    if (i < n4) {
        float4 v = ((const float4*)src)[i];
        __half2 h0 = __floats2half2_rn(v.x, v.y);
        __half2 h1 = __floats2half2_rn(v.z, v.w);
        uint2 u;
        u.x = *reinterpret_cast<uint32_t*>(&h0);
        u.y = *reinterpret_cast<uint32_t*>(&h1);
        ((uint2*)dst)[i] = u;
    }
}

// ---------------------------------------------------------------------------
// fp16 tensor GEMM: C[M,N] = A[M,K] @ W[N,K]^T + bias.
// mode 0: fp16 out   mode 1: ReLU fp16 out
// mode 2: fused residual+LN (N==128): X <- LN(X + gemm + bias)*gamma+beta + Xh mirror
// Tile 128x128, K staged in chunks of 128 (whole K for K=128 -> ZERO mainloop
// barriers; K=512 -> 4 double-buffered stages). 256 threads, 8 warps x 64x32.
// ---------------------------------------------------------------------------
#define BK    128
#define ALD   136                        // halves per smem row (128+8 pad)
#define OP_B  34816                      // bytes per operand tile (128*136*2)
#define STG_B (2*OP_B)                   // 69632 bytes per stage
#define CLD   132

__device__ __forceinline__ uint32_t smem_u32(const void* p) {
    uint32_t a;
    asm("{ .reg .u64 t; cvta.to.shared.u64 t, %1; cvt.u32.u64 %0, t; }"
        : "=r"(a) : "l"(p));
    return a;
}
__device__ __forceinline__ void cp16(uint32_t dst, const void* src) {
    asm volatile("cp.async.ca.shared.global [%0], [%1], 16;" :: "r"(dst), "l"(src));
}

__device__ __forceinline__ void issue_stage(
    uint32_t sb, const __half* A, const __half* W,
    size_t bm, size_t bn, int K, int kk, int tid)
{
#pragma unroll
    for (int p = 0; p < 8; p++) {
        const int chunk = tid + p * 256;       // 0..2047
        const int row = chunk >> 4;
        const int col = chunk & 15;            // 8-half chunk
        cp16(sb + row * (ALD * 2) + col * 16, A + (bm + row) * K + kk + col * 8);
        cp16(sb + OP_B + row * (ALD * 2) + col * 16, W + (bn + row) * K + kk + col * 8);
    }
    asm volatile("cp.async.commit_group;");
}

__global__ __launch_bounds__(256) void gemm_h(
    const __half* __restrict__ A, const __half* __restrict__ W,
    const float* __restrict__ bias,
    __half* __restrict__ Ch,                       // modes 0/1
    float* __restrict__ X, __half* __restrict__ Xh,// mode 2
    const float* __restrict__ gamma, const float* __restrict__ beta,
    int N, int K, int mode)
{
    extern __shared__ __align__(16) char smem[];
    const uint32_t sbase = smem_u32(smem);
    const int tid  = threadIdx.x;
    const int wid  = tid >> 5;
    const int lane = tid & 31;
    const int wm   = wid & 1;            // 64-row group
    const int wn   = wid >> 1;           // 32-col group
    const size_t bm = (size_t)blockIdx.y * 128;
    const size_t bn = (size_t)blockIdx.x * 128;
    const int NT = K / BK;               // 1 (K=128) or 4 (K=512)

    wmma::fragment<wmma::accumulator, 16, 16, 16, float> acc[4][2];
#pragma unroll
    for (int i = 0; i < 4; i++)
#pragma unroll
        for (int j = 0; j < 2; j++) wmma::fill_fragment(acc[i][j], 0.f);

    // prologue: stage 0
    issue_stage(sbase, A, W, bm, bn, K, 0, tid);

    for (int t = 0; t < NT; t++) {
        asm volatile("cp.async.wait_group 0;");
        __syncthreads();
        if (t + 1 < NT)
            issue_stage(sbase + ((t + 1) & 1) * STG_B, A, W, bm, bn, K, (t + 1) * BK, tid);
        // compute stage t: 8 k-steps, no barriers
        {
            const __half* As = (const __half*)(smem + (t & 1) * STG_B);
            const __half* Ws = As + 128 * ALD;
#pragma unroll
            for (int ks = 0; ks < 8; ks++) {
                wmma::fragment<wmma::matrix_a, 16, 16, 16, __half, wmma::row_major> af[4];
                wmma::fragment<wmma::matrix_b, 16, 16, 16, __half, wmma::col_major> bf[2];
#pragma unroll
                for (int i = 0; i < 4; i++)
                    wmma::load_matrix_sync(af[i], As + (wm * 64 + i * 16) * ALD + ks * 16, ALD);
#pragma unroll
                for (int j = 0; j < 2; j++)
                    wmma::load_matrix_sync(bf[j], Ws + (wn * 32 + j * 16) * ALD + ks * 16, ALD);
#pragma unroll
                for (int i = 0; i < 4; i++)
#pragma unroll
                    for (int j = 0; j < 2; j++)
                        wmma::mma_sync(acc[i][j], af[i], bf[j], acc[i][j]);
            }
        }
        if (t + 1 < NT) __syncthreads();   // readers done before next-next overwrite
    }
    __syncthreads();

    // Epilogue: stage f32 accumulators in smem (aliases stage buffers)
    float* smf = (float*)smem;
#pragma unroll
    for (int i = 0; i < 4; i++)
#pragma unroll
        for (int j = 0; j < 2; j++)
            wmma::store_matrix_sync(smf + (wm * 64 + i * 16) * CLD + wn * 32 + j * 16,
                                    acc[i][j], CLD, wmma::mem_row_major);
    __syncthreads();

    if (mode == 2) {
        // fused residual + LayerNorm (N==128, bn==0); warp per row, 16 rows/warp
        float4 gv = *(const float4*)(gamma + lane * 4);
        float4 bv = *(const float4*)(beta  + lane * 4);
        float4 bz = *(const float4*)(bias  + lane * 4);
#pragma unroll
        for (int i = 0; i < 16; i++) {
            const int row = wid * 16 + i;
            float4 v = *(float4*)(smf + row * CLD + lane * 4);
            const size_t off = (bm + row) * DD + lane * 4;
            float4 xv = *(const float4*)(X + off);
            float4 tv;
            tv.x = v.x + bz.x + xv.x; tv.y = v.y + bz.y + xv.y;
            tv.z = v.z + bz.z + xv.z; tv.w = v.w + bz.w + xv.w;
            float s  = tv.x + tv.y + tv.z + tv.w;
            float s2 = tv.x*tv.x + tv.y*tv.y + tv.z*tv.z + tv.w*tv.w;
#pragma unroll
            for (int o = 16; o > 0; o >>= 1) {
                s  += __shfl_xor_sync(0xffffffffu, s,  o);
                s2 += __shfl_xor_sync(0xffffffffu, s2, o);
            }
            float mean = s * (1.f / DD);
            float var  = s2 * (1.f / DD) - mean * mean;
            float rstd = rsqrtf(var + 1e-5f);
            float4 y;
            y.x = (tv.x - mean) * rstd * gv.x + bv.x;
            y.y = (tv.y - mean) * rstd * gv.y + bv.y;
            y.z = (tv.z - mean) * rstd * gv.z + bv.z;
            y.w = (tv.w - mean) * rstd * gv.w + bv.w;
            *(float4*)(X + off) = y;
            __half2 h0 = __floats2half2_rn(y.x, y.y);
            __half2 h1 = __floats2half2_rn(y.z, y.w);
            uint2 u;
            u.x = *reinterpret_cast<uint32_t*>(&h0);
            u.y = *reinterpret_cast<uint32_t*>(&h1);
            *(uint2*)(Xh + off) = u;
        }
    } else {
        // bias (+ReLU), fp16 out: 4096 float4 reads, 16/thread
#pragma unroll
        for (int i = 0; i < 16; i++) {
            int idx = i * 256 + tid;
            int row = idx >> 5;
            int cc  = (idx & 31) * 4;
            float4 v  = *(float4*)(smf + row * CLD + cc);
            float4 bz = *(const float4*)(bias + bn + cc);
            v.x += bz.x; v.y += bz.y; v.z += bz.z; v.w += bz.w;
            if (mode == 1) {
                v.x = fmaxf(v.x, 0.f); v.y = fmaxf(v.y, 0.f);
                v.z = fmaxf(v.z, 0.f); v.w = fmaxf(v.w, 0.f);
            }
            __half2 h0 = __floats2half2_rn(v.x, v.y);
            __half2 h1 = __floats2half2_rn(v.z, v.w);
            uint2 u;
            u.x = *reinterpret_cast<uint32_t*>(&h0);
            u.y = *reinterpret_cast<uint32_t*>(&h1);
            *(uint2*)(Ch + (bm + row) * N + bn + cc) = u;
        }
    }
}

// ---------------------------------------------------------------------------
// Fast exp (FFMA-only)
// ---------------------------------------------------------------------------
__device__ __forceinline__ float fast_exp(float x) {
    x = fmaxf(x, -80.f);
    float t  = x * 1.4426950408889634f;
    float fn = t + 12582912.f;
    int   ni = __float_as_int(fn) - 0x4B400000;
    float r  = t - (fn - 12582912.f);
    float p  = 0.00133336f;
    p = fmaf(p, r, 0.00961813f);
    p = fmaf(p, r, 0.05550411f);
    p = fmaf(p, r, 0.24022651f);
    p = fmaf(p, r, 0.69314718f);
    p = fmaf(p, r, 1.0f);
    return p * __int_as_float((ni + 127) << 23);
}

// ---------------------------------------------------------------------------
// Attention: fp16 qkv in, fp16 out; fp32 math. One block per (b,h).
// ---------------------------------------------------------------------------
__global__ __launch_bounds__(128) void attn_kernel(
    const __half* __restrict__ qkv, const float* __restrict__ mask,
    __half* __restrict__ out)
{
    const int h = blockIdx.x;
    const int b = blockIdx.y;
    const int t = threadIdx.x;

    __shared__ float ks[TT][HDIM];
    __shared__ float vs[TT][HDIM];
    __shared__ float ms[TT];

    const __half* base = qkv + (size_t)b * TT * 3 * DD;
    {
        const __half* kr = base + (size_t)t * 3 * DD + DD + h * HDIM;
        const __half* vr = kr + DD;
#pragma unroll
        for (int c = 0; c < 2; c++) {
            uint4 rk = ((const uint4*)kr)[c];
            uint4 rv = ((const uint4*)vr)[c];
            const uint32_t* pk = &rk.x;
            const uint32_t* pv = &rv.x;
#pragma unroll
            for (int j = 0; j < 4; j++) {
                float2 fk = __half22float2(*(const __half2*)&pk[j]);
                float2 fv = __half22float2(*(const __half2*)&pv[j]);
                ks[t][c * 8 + j * 2]     = fk.x;
                ks[t][c * 8 + j * 2 + 1] = fk.y;
                vs[t][c * 8 + j * 2]     = fv.x;
                vs[t][c * 8 + j * 2 + 1] = fv.y;
            }
        }
        ms[t] = mask[b * TT + t];
    }
    __syncthreads();

    float q[HDIM];
    {
        const __half* qr = base + (size_t)t * 3 * DD + h * HDIM;
#pragma unroll
        for (int c = 0; c < 2; c++) {
            uint4 rq = ((const uint4*)qr)[c];
            const uint32_t* pq = &rq.x;
#pragma unroll
            for (int j = 0; j < 4; j++) {
                float2 fq = __half22float2(*(const __half2*)&pq[j]);
                q[c * 8 + j * 2]     = fq.x;
                q[c * 8 + j * 2 + 1] = fq.y;
            }
        }
    }

    const float scale = 0.25f;
    float s = 0.f;
    float o[HDIM];
#pragma unroll
    for (int c = 0; c < HDIM; c++) o[c] = 0.f;

    for (int j = 0; j < TT; j++) {
        float d = 0.f;
#pragma unroll
        for (int c = 0; c < HDIM; c++) d = fmaf(q[c], ks[j][c], d);
        float p = fast_exp(fmaf(d, scale, ms[j]));
        s += p;
#pragma unroll
        for (int c = 0; c < HDIM; c++) o[c] = fmaf(p, vs[j][c], o[c]);
    }
    float inv = 1.f / s;
    __half* op = out + (size_t)(b * TT + t) * DD + h * HDIM;
    uint4 w[2];
#pragma unroll
    for (int c = 0; c < 2; c++) {
        uint32_t* pw = &w[c].x;
#pragma unroll
        for (int j = 0; j < 4; j++) {
            __half2 hv = __floats2half2_rn(o[c * 8 + j * 2] * inv,
                                           o[c * 8 + j * 2 + 1] * inv);
            pw[j] = *reinterpret_cast<uint32_t*>(&hv);
        }
        ((uint4*)op)[c] = w[c];
    }
}

// ---------------------------------------------------------------------------
extern "C" void kernel_launch(void* const* d_in, const int* in_sizes, int n_in,
                              void* d_out, int out_size)
{
    const float* x_in      = (const float*)d_in[0];
    const float* mask      = (const float*)d_in[1];
    const float* in_proj_w = (const float*)d_in[2];
    const float* in_proj_b = (const float*)d_in[3];
    const float* out_w     = (const float*)d_in[4];
    const float* out_b     = (const float*)d_in[5];
    const float* ln1_g     = (const float*)d_in[6];
    const float* ln1_b     = (const float*)d_in[7];
    const float* ff1_w     = (const float*)d_in[8];
    const float* ff1_b     = (const float*)d_in[9];
    const float* ff2_w     = (const float*)d_in[10];
    const float* ff2_b     = (const float*)d_in[11];
    const float* ln2_g     = (const float*)d_in[12];
    const float* ln2_b     = (const float*)d_in[13];
    float* x = (float*)d_out;

    __half *wqkv, *wout, *wff1, *wff2, *xh, *qkvh, *attnh, *hh;
    cudaGetSymbolAddress((void**)&wqkv, g_wqkv);
    cudaGetSymbolAddress((void**)&wout, g_wout);
    cudaGetSymbolAddress((void**)&wff1, g_wff1);
    cudaGetSymbolAddress((void**)&wff2, g_wff2);
    cudaGetSymbolAddress((void**)&xh,   g_xh);
    cudaGetSymbolAddress((void**)&qkvh, g_qkvh);
    cudaGetSymbolAddress((void**)&attnh,g_attnh);
    cudaGetSymbolAddress((void**)&hh,   g_hh);

    const int smem1 = STG_B;          // K=128: single stage (69632 B)
    const int smem2 = 2 * STG_B;      // K=512: double buffer (139264 B)
    cudaFuncSetAttribute(gemm_h, cudaFuncAttributeMaxDynamicSharedMemorySize, smem2);

    cudaMemcpyAsync(x, x_in, sizeof(float) * (size_t)MM * DD,
                    cudaMemcpyDeviceToDevice);
    {
        int n;
        n = NL * 3 * DD * DD / 4; cvt_f2h<<<(n + 255) / 256, 256>>>(in_proj_w, wqkv, n);
        n = NL * DD * DD / 4;     cvt_f2h<<<(n + 255) / 256, 256>>>(out_w,  wout, n);
        n = NL * FFD * DD / 4;    cvt_f2h<<<(n + 255) / 256, 256>>>(ff1_w,  wff1, n);
        n = NL * DD * FFD / 4;    cvt_f2h<<<(n + 255) / 256, 256>>>(ff2_w,  wff2, n);
        n = MM * DD / 4;          cvt_f2h<<<(n + 255) / 256, 256>>>(x_in,   xh,   n);
    }

    for (int l = 0; l < NL; l++) {
        // qkv = x @ Wqkv^T + b   [MM, 384] fp16
        gemm_h<<<dim3(3, MM / 128), 256, smem1>>>(
            xh, wqkv + (size_t)l * 3 * DD * DD, in_proj_b + (size_t)l * 3 * DD,
            qkvh, nullptr, nullptr, nullptr, nullptr, 3 * DD, DD, 0);
        // attention -> attnh [MM, DD] fp16
        attn_kernel<<<dim3(HH, BB), 128>>>(qkvh, mask, attnh);
        // x = LN(x + attnh @ out_w^T + out_b); xh mirror
        gemm_h<<<dim3(1, MM / 128), 256, smem1>>>(
            attnh, wout + (size_t)l * DD * DD, out_b + (size_t)l * DD,
            nullptr, x, xh, ln1_g + (size_t)l * DD, ln1_b + (size_t)l * DD, DD, DD, 2);
        // h = relu(x @ ff1_w^T + b) -> hh [MM, FFD] fp16
        gemm_h<<<dim3(4, MM / 128), 256, smem1>>>(
            xh, wff1 + (size_t)l * FFD * DD, ff1_b + (size_t)l * FFD,
            hh, nullptr, nullptr, nullptr, nullptr, FFD, DD, 1);
        // x = LN(x + hh @ ff2_w^T + b); xh mirror
        gemm_h<<<dim3(1, MM / 128), 256, smem2>>>(
            hh, wff2 + (size_t)l * DD * FFD, ff2_b + (size_t)l * DD,
            nullptr, x, xh, ln2_g + (size_t)l * DD, ln2_b + (size_t)l * DD, DD, FFD, 2);
    }
}

// round 8
// speedup vs baseline: 1.2718x; 1.1940x over previous
#include <cuda_runtime.h>
#include <cuda_fp16.h>
#include <mma.h>
#include <cstdint>
using namespace nvcuda;

// Problem dims (fixed)
#define BB   1024
#define TT   128
#define DD   128
#define HH   8
#define HDIM 16
#define FFD  512
#define NL   2
#define MM   (BB*TT)          // 131072 tokens

// fp16 scratch (device globals: allocation-free per harness rules)
__device__ __half g_wqkv[(size_t)NL * 3 * DD * DD];
__device__ __half g_wout[(size_t)NL * DD * DD];
__device__ __half g_wff1[(size_t)NL * FFD * DD];
__device__ __half g_wff2[(size_t)NL * DD * FFD];
__device__ __half g_xh  [(size_t)MM * DD];        // fp16 mirror of x
__device__ __half g_qkvh[(size_t)MM * 3 * DD];
__device__ __half g_attnh[(size_t)MM * DD];
__device__ __half g_hh  [(size_t)MM * FFD];

// ---------------------------------------------------------------------------
__global__ void cvt_f2h(const float* __restrict__ src, __half* __restrict__ dst, int n4) {
    int i = blockIdx.x * blockDim.x + threadIdx.x;
    if (i < n4) {
        float4 v = ((const float4*)src)[i];
        __half2 h0 = __floats2half2_rn(v.x, v.y);
        __half2 h1 = __floats2half2_rn(v.z, v.w);
        uint2 u;
        u.x = *reinterpret_cast<uint32_t*>(&h0);
        u.y = *reinterpret_cast<uint32_t*>(&h1);
        ((uint2*)dst)[i] = u;
    }
}

// ---------------------------------------------------------------------------
// fp16 tensor GEMM (R5 measured-best config): C = A @ W^T + bias.
// mode 0: fp16 out   mode 1: ReLU fp16 out
// mode 2: fused residual+LN (N==128): X <- LN(X + gemm + bias)*gamma+beta + Xh mirror
// Tile 128x128, BK=32, 4-stage cp.async, 256 threads, 8 warps x 64x32.
// ---------------------------------------------------------------------------
#define BK   32
#define ALD  40
#define STG_B 20480
#define NS   4
#define CLD  132
#define SMEM_DYN (NS*STG_B)

__device__ __forceinline__ uint32_t smem_u32(const void* p) {
    uint32_t a;
    asm("{ .reg .u64 t; cvta.to.shared.u64 t, %1; cvt.u32.u64 %0, t; }"
        : "=r"(a) : "l"(p));
    return a;
}
__device__ __forceinline__ void cp16(uint32_t dst, const void* src) {
    asm volatile("cp.async.ca.shared.global [%0], [%1], 16;" :: "r"(dst), "l"(src));
}

__global__ __launch_bounds__(256) void gemm_h(
    const __half* __restrict__ A, const __half* __restrict__ W,
    const float* __restrict__ bias,
    __half* __restrict__ Ch,
    float* __restrict__ X, __half* __restrict__ Xh,
    const float* __restrict__ gamma, const float* __restrict__ beta,
    int N, int K, int mode)
{
    extern __shared__ __align__(16) char smem[];
    const uint32_t sbase = smem_u32(smem);
    const int tid  = threadIdx.x;
    const int wid  = tid >> 5;
    const int lane = tid & 31;
    const int wm   = wid & 1;
    const int wn   = wid >> 1;
    const size_t bm = (size_t)blockIdx.y * 128;
    const size_t bn = (size_t)blockIdx.x * 128;
    const int NT = K / BK;

    const int ch0 = tid, ch1 = tid + 256;
    const int rA0 = ch0 >> 2, cA0 = ch0 & 3;
    const int rA1 = ch1 >> 2, cA1 = ch1 & 3;

    wmma::fragment<wmma::accumulator, 16, 16, 16, float> acc[4][2];
#pragma unroll
    for (int i = 0; i < 4; i++)
#pragma unroll
        for (int j = 0; j < 2; j++) wmma::fill_fragment(acc[i][j], 0.f);

#pragma unroll
    for (int t = 0; t < NS - 1; t++) {
        if (t < NT) {
            const int kk = t * BK;
            const uint32_t sb = sbase + (t % NS) * STG_B;
            cp16(sb + (rA0 * ALD + cA0 * 8) * 2, A + (bm + rA0) * K + kk + cA0 * 8);
            cp16(sb + (rA1 * ALD + cA1 * 8) * 2, A + (bm + rA1) * K + kk + cA1 * 8);
            cp16(sb + 10240 + (rA0 * ALD + cA0 * 8) * 2, W + (bn + rA0) * K + kk + cA0 * 8);
            cp16(sb + 10240 + (rA1 * ALD + cA1 * 8) * 2, W + (bn + rA1) * K + kk + cA1 * 8);
        }
        asm volatile("cp.async.commit_group;");
    }

    for (int t = 0; t < NT; t++) {
        asm volatile("cp.async.wait_group %0;" :: "n"(NS - 2));
        __syncthreads();
        {
            const __half* As = (const __half*)(smem + (t % NS) * STG_B);
            const __half* Ws = As + 5120;
#pragma unroll
            for (int ks = 0; ks < 2; ks++) {
                wmma::fragment<wmma::matrix_a, 16, 16, 16, __half, wmma::row_major> af[4];
                wmma::fragment<wmma::matrix_b, 16, 16, 16, __half, wmma::col_major> bf[2];
#pragma unroll
                for (int i = 0; i < 4; i++)
                    wmma::load_matrix_sync(af[i], As + (wm * 64 + i * 16) * ALD + ks * 16, ALD);
#pragma unroll
                for (int j = 0; j < 2; j++)
                    wmma::load_matrix_sync(bf[j], Ws + (wn * 32 + j * 16) * ALD + ks * 16, ALD);
#pragma unroll
                for (int i = 0; i < 4; i++)
#pragma unroll
                    for (int j = 0; j < 2; j++)
                        wmma::mma_sync(acc[i][j], af[i], bf[j], acc[i][j]);
            }
        }
        __syncthreads();
        {
            const int tn = t + NS - 1;
            if (tn < NT) {
                const int kk = tn * BK;
                const uint32_t sb = sbase + (tn % NS) * STG_B;
                cp16(sb + (rA0 * ALD + cA0 * 8) * 2, A + (bm + rA0) * K + kk + cA0 * 8);
                cp16(sb + (rA1 * ALD + cA1 * 8) * 2, A + (bm + rA1) * K + kk + cA1 * 8);
                cp16(sb + 10240 + (rA0 * ALD + cA0 * 8) * 2, W + (bn + rA0) * K + kk + cA0 * 8);
                cp16(sb + 10240 + (rA1 * ALD + cA1 * 8) * 2, W + (bn + rA1) * K + kk + cA1 * 8);
            }
            asm volatile("cp.async.commit_group;");
        }
    }

    float* smf = (float*)smem;
#pragma unroll
    for (int i = 0; i < 4; i++)
#pragma unroll
        for (int j = 0; j < 2; j++)
            wmma::store_matrix_sync(smf + (wm * 64 + i * 16) * CLD + wn * 32 + j * 16,
                                    acc[i][j], CLD, wmma::mem_row_major);
    __syncthreads();

    if (mode == 2) {
        float4 gv = *(const float4*)(gamma + lane * 4);
        float4 bv = *(const float4*)(beta  + lane * 4);
        float4 bz = *(const float4*)(bias  + lane * 4);
#pragma unroll
        for (int i = 0; i < 16; i++) {
            const int row = wid * 16 + i;
            float4 v = *(float4*)(smf + row * CLD + lane * 4);
            const size_t off = (bm + row) * DD + lane * 4;
            float4 xv = *(const float4*)(X + off);
            float4 tv;
            tv.x = v.x + bz.x + xv.x; tv.y = v.y + bz.y + xv.y;
            tv.z = v.z + bz.z + xv.z; tv.w = v.w + bz.w + xv.w;
            float s  = tv.x + tv.y + tv.z + tv.w;
            float s2 = tv.x*tv.x + tv.y*tv.y + tv.z*tv.z + tv.w*tv.w;
#pragma unroll
            for (int o = 16; o > 0; o >>= 1) {
                s  += __shfl_xor_sync(0xffffffffu, s,  o);
                s2 += __shfl_xor_sync(0xffffffffu, s2, o);
            }
            float mean = s * (1.f / DD);
            float var  = s2 * (1.f / DD) - mean * mean;
            float rstd = rsqrtf(var + 1e-5f);
            float4 y;
            y.x = (tv.x - mean) * rstd * gv.x + bv.x;
            y.y = (tv.y - mean) * rstd * gv.y + bv.y;
            y.z = (tv.z - mean) * rstd * gv.z + bv.z;
            y.w = (tv.w - mean) * rstd * gv.w + bv.w;
            *(float4*)(X + off) = y;
            __half2 h0 = __floats2half2_rn(y.x, y.y);
            __half2 h1 = __floats2half2_rn(y.z, y.w);
            uint2 u;
            u.x = *reinterpret_cast<uint32_t*>(&h0);
            u.y = *reinterpret_cast<uint32_t*>(&h1);
            *(uint2*)(Xh + off) = u;
        }
    } else {
#pragma unroll
        for (int i = 0; i < 16; i++) {
            int idx = i * 256 + tid;
            int row = idx >> 5;
            int cc  = (idx & 31) * 4;
            float4 v  = *(float4*)(smf + row * CLD + cc);
            float4 bz = *(const float4*)(bias + bn + cc);
            v.x += bz.x; v.y += bz.y; v.z += bz.z; v.w += bz.w;
            if (mode == 1) {
                v.x = fmaxf(v.x, 0.f); v.y = fmaxf(v.y, 0.f);
                v.z = fmaxf(v.z, 0.f); v.w = fmaxf(v.w, 0.f);
            }
            __half2 h0 = __floats2half2_rn(v.x, v.y);
            __half2 h1 = __floats2half2_rn(v.z, v.w);
            uint2 u;
            u.x = *reinterpret_cast<uint32_t*>(&h0);
            u.y = *reinterpret_cast<uint32_t*>(&h1);
            *(uint2*)(Ch + (bm + row) * N + bn + cc) = u;
        }
    }
}

// ---------------------------------------------------------------------------
// Fast exp scaled by 2^-6 (exponent-bias trick; FFMA-only)
// ---------------------------------------------------------------------------
__device__ __forceinline__ float fast_exp_s6(float x) {
    x = fmaxf(x, -80.f);
    float t  = x * 1.4426950408889634f;
    float fn = t + 12582912.f;
    int   ni = __float_as_int(fn) - 0x4B400000;
    float r  = t - (fn - 12582912.f);
    float p  = 0.00133336f;
    p = fmaf(p, r, 0.00961813f);
    p = fmaf(p, r, 0.05550411f);
    p = fmaf(p, r, 0.24022651f);
    p = fmaf(p, r, 0.69314718f);
    p = fmaf(p, r, 1.0f);
    return p * __int_as_float((ni + 121) << 23);   // * 2^(n-6)
}

// ---------------------------------------------------------------------------
// Tensor-core attention. One block per (b,h), 256 threads / 8 warps.
// S = Q@K^T by wmma (HDIM=16 = one k-step), two 64-col chunks through smem;
// exp (scaled 2^-6) -> P fp16; O = P@V by wmma; normalize; fp16 out.
// smem 89088 B -> 2 CTAs/SM.
// ---------------------------------------------------------------------------
#define QLD 24
#define SLD 68
#define PLD 136
#define OLD 20
#define ATT_SMEM 89088

__global__ __launch_bounds__(256, 2) void attn_tc(
    const __half* __restrict__ qkv, const float* __restrict__ mask,
    __half* __restrict__ out)
{
    extern __shared__ __align__(16) char asmem[];
    __half* Qs = (__half*)(asmem);                 // 128 x QLD
    __half* Ks = (__half*)(asmem + 6144);
    __half* Vs = (__half*)(asmem + 12288);
    float*  ms = (float*) (asmem + 18432);         // 128
    float*  rs = (float*) (asmem + 18944);         // 128
    float*  Ss = (float*) (asmem + 19456);         // 128 x SLD
    __half* Ps = (__half*)(asmem + 54272);         // 128 x PLD
    float*  Os = (float*) (asmem);                 // aliases Qs/Ks after S phase

    const int h = blockIdx.x & 7;
    const int b = blockIdx.x >> 3;
    const int tid = threadIdx.x, wid = tid >> 5;

    // load Q/K/V head slices + mask
    {
        const int row = tid >> 1, ch = tid & 1;
        const __half* base = qkv + ((size_t)b * TT + row) * (3 * DD) + h * HDIM + ch * 8;
        *(uint4*)(Qs + row * QLD + ch * 8) = *(const uint4*)(base);
        *(uint4*)(Ks + row * QLD + ch * 8) = *(const uint4*)(base + DD);
        *(uint4*)(Vs + row * QLD + ch * 8) = *(const uint4*)(base + 2 * DD);
        if (tid < TT) ms[tid] = mask[b * TT + tid];
    }
    __syncthreads();

    // A fragment (Q rows for this warp) - reused for both chunks
    wmma::fragment<wmma::matrix_a, 16, 16, 16, __half, wmma::row_major> qf;
    wmma::load_matrix_sync(qf, Qs + wid * 16 * QLD, QLD);

    float sum = 0.f;                   // per-thread partial rowsum
    const int er = tid >> 1;           // exp row
    const int eh = tid & 1;            // col half within chunk

    for (int chunk = 0; chunk < 2; chunk++) {
        // S chunk: 128 rows x 64 cols
#pragma unroll
        for (int j = 0; j < 4; j++) {
            wmma::fragment<wmma::matrix_b, 16, 16, 16, __half, wmma::col_major> kf;
            wmma::fragment<wmma::accumulator, 16, 16, 16, float> sf;
            wmma::load_matrix_sync(kf, Ks + (chunk * 64 + j * 16) * QLD, QLD);
            wmma::fill_fragment(sf, 0.f);
            wmma::mma_sync(sf, qf, kf, sf);
            wmma::store_matrix_sync(Ss + (wid * 16) * SLD + j * 16, sf, SLD, wmma::mem_row_major);
        }
        __syncthreads();
        // exp + accumulate rowsum, write P fp16
        {
            const float* srow = Ss + er * SLD + eh * 32;
            __half* prow = Ps + er * PLD + chunk * 64 + eh * 32;
            const float* mrow = ms + chunk * 64 + eh * 32;
#pragma unroll
            for (int c = 0; c < 32; c++) {
                float p = fast_exp_s6(fmaf(srow[c], 0.25f, mrow[c]));
                __half ph = __float2half_rn(p);
                prow[c] = ph;
                sum += __half2float(ph);
            }
        }
        __syncthreads();   // Ss free for next chunk
    }
    // finish rowsum (2 threads per row)
    sum += __shfl_xor_sync(0xffffffffu, sum, 1);
    if (!eh) rs[er] = sum;
    __syncthreads();

    // O = P @ V  (per warp: 16 rows x 16 cols, K=128)
    {
        wmma::fragment<wmma::accumulator, 16, 16, 16, float> of;
        wmma::fill_fragment(of, 0.f);
#pragma unroll
        for (int j = 0; j < 8; j++) {
            wmma::fragment<wmma::matrix_a, 16, 16, 16, __half, wmma::row_major> pf;
            wmma::fragment<wmma::matrix_b, 16, 16, 16, __half, wmma::row_major> vf;
            wmma::load_matrix_sync(pf, Ps + (wid * 16) * PLD + j * 16, PLD);
            wmma::load_matrix_sync(vf, Vs + (j * 16) * QLD, QLD);
            wmma::mma_sync(of, pf, vf, of);
        }
        wmma::store_matrix_sync(Os + (wid * 16) * OLD, of, OLD, wmma::mem_row_major);
    }
    __syncthreads();

    // normalize + write fp16
    {
        const int r = tid >> 1, c0 = (tid & 1) * 8;
        const float inv = 1.f / rs[r];
        const float* orow = Os + r * OLD + c0;
        uint4 u;
        uint32_t* pu = &u.x;
#pragma unroll
        for (int j = 0; j < 4; j++) {
            __half2 hv = __floats2half2_rn(orow[j * 2] * inv, orow[j * 2 + 1] * inv);
            pu[j] = *reinterpret_cast<uint32_t*>(&hv);
        }
        *(uint4*)(out + ((size_t)b * TT + r) * DD + h * HDIM + c0) = u;
    }
}

// ---------------------------------------------------------------------------
extern "C" void kernel_launch(void* const* d_in, const int* in_sizes, int n_in,
                              void* d_out, int out_size)
{
    const float* x_in      = (const float*)d_in[0];
    const float* mask      = (const float*)d_in[1];
    const float* in_proj_w = (const float*)d_in[2];
    const float* in_proj_b = (const float*)d_in[3];
    const float* out_w     = (const float*)d_in[4];
    const float* out_b     = (const float*)d_in[5];
    const float* ln1_g     = (const float*)d_in[6];
    const float* ln1_b     = (const float*)d_in[7];
    const float* ff1_w     = (const float*)d_in[8];
    const float* ff1_b     = (const float*)d_in[9];
    const float* ff2_w     = (const float*)d_in[10];
    const float* ff2_b     = (const float*)d_in[11];
    const float* ln2_g     = (const float*)d_in[12];
    const float* ln2_b     = (const float*)d_in[13];
    float* x = (float*)d_out;

    __half *wqkv, *wout, *wff1, *wff2, *xh, *qkvh, *attnh, *hh;
    cudaGetSymbolAddress((void**)&wqkv, g_wqkv);
    cudaGetSymbolAddress((void**)&wout, g_wout);
    cudaGetSymbolAddress((void**)&wff1, g_wff1);
    cudaGetSymbolAddress((void**)&wff2, g_wff2);
    cudaGetSymbolAddress((void**)&xh,   g_xh);
    cudaGetSymbolAddress((void**)&qkvh, g_qkvh);
    cudaGetSymbolAddress((void**)&attnh,g_attnh);
    cudaGetSymbolAddress((void**)&hh,   g_hh);

    cudaFuncSetAttribute(gemm_h, cudaFuncAttributeMaxDynamicSharedMemorySize, SMEM_DYN);
    cudaFuncSetAttribute(attn_tc, cudaFuncAttributeMaxDynamicSharedMemorySize, ATT_SMEM);

    cudaMemcpyAsync(x, x_in, sizeof(float) * (size_t)MM * DD,
                    cudaMemcpyDeviceToDevice);
    {
        int n;
        n = MM * DD / 4;          cvt_f2h<<<(n + 255) / 256, 256>>>(x_in,   xh,   n);
        n = NL * 3 * DD * DD / 4; cvt_f2h<<<(n + 255) / 256, 256>>>(in_proj_w, wqkv, n);
        n = NL * DD * DD / 4;     cvt_f2h<<<(n + 255) / 256, 256>>>(out_w,  wout, n);
        n = NL * FFD * DD / 4;    cvt_f2h<<<(n + 255) / 256, 256>>>(ff1_w,  wff1, n);
        n = NL * DD * FFD / 4;    cvt_f2h<<<(n + 255) / 256, 256>>>(ff2_w,  wff2, n);
    }

    for (int l = 0; l < NL; l++) {
        // qkv = x @ Wqkv^T + b   [MM, 384] fp16
        gemm_h<<<dim3(3, MM / 128), 256, SMEM_DYN>>>(
            xh, wqkv + (size_t)l * 3 * DD * DD, in_proj_b + (size_t)l * 3 * DD,
            qkvh, nullptr, nullptr, nullptr, nullptr, 3 * DD, DD, 0);
        // attention -> attnh [MM, DD] fp16 (tensor-core)
        attn_tc<<<BB * HH, 256, ATT_SMEM>>>(qkvh, mask, attnh);
        // x = LN(x + attnh @ out_w^T + out_b); xh mirror
        gemm_h<<<dim3(1, MM / 128), 256, SMEM_DYN>>>(
            attnh, wout + (size_t)l * DD * DD, out_b + (size_t)l * DD,
            nullptr, x, xh, ln1_g + (size_t)l * DD, ln1_b + (size_t)l * DD, DD, DD, 2);
        // h = relu(x @ ff1_w^T + b) -> hh [MM, FFD] fp16
        gemm_h<<<dim3(4, MM / 128), 256, SMEM_DYN>>>(
            xh, wff1 + (size_t)l * FFD * DD, ff1_b + (size_t)l * FFD,
            hh, nullptr, nullptr, nullptr, nullptr, FFD, DD, 1);
        // x = LN(x + hh @ ff2_w^T + b); xh mirror
        gemm_h<<<dim3(1, MM / 128), 256, SMEM_DYN>>>(
            hh, wff2 + (size_t)l * DD * FFD, ff2_b + (size_t)l * DD,
            nullptr, x, xh, ln2_g + (size_t)l * DD, ln2_b + (size_t)l * DD, DD, FFD, 2);
    }
}

// round 9
// speedup vs baseline: 1.2920x; 1.0159x over previous
#include <cuda_runtime.h>
#include <cuda_fp16.h>
#include <mma.h>
#include <cstdint>
using namespace nvcuda;

// Problem dims (fixed)
#define BB   1024
#define TT   128
#define DD   128
#define HH   8
#define HDIM 16
#define FFD  512
#define NL   2
#define MM   (BB*TT)          // 131072 tokens

// fp16 scratch (device globals: allocation-free per harness rules)
__device__ __half g_wqkv[(size_t)NL * 3 * DD * DD];
__device__ __half g_wout[(size_t)NL * DD * DD];
__device__ __half g_wff1[(size_t)NL * FFD * DD];
__device__ __half g_wff2[(size_t)NL * DD * FFD];
__device__ __half g_xh  [(size_t)MM * DD];        // fp16 mirror of x
__device__ __half g_qkvh[(size_t)MM * 3 * DD];
__device__ __half g_attnh[(size_t)MM * DD];
__device__ __half g_hh  [(size_t)MM * FFD];

// ---------------------------------------------------------------------------
// Single conversion kernel: x + all weights -> fp16 (segmented index space)
// ---------------------------------------------------------------------------
#define N_XH4 (MM * DD / 4)                   // 4194304
#define N_WQ4 (NL * 3 * DD * DD / 4)          // 24576
#define N_WO4 (NL * DD * DD / 4)              // 8192
#define N_W14 (NL * FFD * DD / 4)             // 32768
#define N_W24 (NL * DD * FFD / 4)             // 32768
#define N_CVT (N_XH4 + N_WQ4 + N_WO4 + N_W14 + N_W24)

__global__ void cvt_all(const float* __restrict__ x,
                        const float* __restrict__ wq,
                        const float* __restrict__ wo,
                        const float* __restrict__ w1,
                        const float* __restrict__ w2)
{
    long i = (long)blockIdx.x * blockDim.x + threadIdx.x;
    if (i >= N_CVT) return;
    const float* src;
    __half* dst;
    long off = i;
    if (off < N_XH4)                      { src = x;  dst = g_xh;   }
    else if ((off -= N_XH4) < N_WQ4)      { src = wq; dst = g_wqkv; }
    else if ((off -= N_WQ4) < N_WO4)      { src = wo; dst = g_wout; }
    else if ((off -= N_WO4) < N_W14)      { src = w1; dst = g_wff1; }
    else  { off -= N_W14;                   src = w2; dst = g_wff2; }
    float4 v = ((const float4*)src)[off];
    __half2 h0 = __floats2half2_rn(v.x, v.y);
    __half2 h1 = __floats2half2_rn(v.z, v.w);
    uint2 u;
    u.x = *reinterpret_cast<uint32_t*>(&h0);
    u.y = *reinterpret_cast<uint32_t*>(&h1);
    ((uint2*)dst)[off] = u;
}

// ---------------------------------------------------------------------------
// fp16 tensor GEMM (R5 shape + forced 2 CTAs/SM): C = A @ W^T + bias.
// mode 0: fp16 out   mode 1: ReLU fp16 out
// mode 2: fused residual+LN (N==128): X <- LN(X + gemm + bias)*gamma+beta + Xh mirror
// Tile 128x128, BK=32, 4-stage cp.async, 256 threads, 8 warps x 64x32.
// ---------------------------------------------------------------------------
#define BK   32
#define ALD  40
#define STG_B 20480
#define NS   4
#define CLD  132
#define SMEM_DYN (NS*STG_B)

__device__ __forceinline__ uint32_t smem_u32(const void* p) {
    uint32_t a;
    asm("{ .reg .u64 t; cvta.to.shared.u64 t, %1; cvt.u32.u64 %0, t; }"
        : "=r"(a) : "l"(p));
    return a;
}
__device__ __forceinline__ void cp16(uint32_t dst, const void* src) {
    asm volatile("cp.async.ca.shared.global [%0], [%1], 16;" :: "r"(dst), "l"(src));
}

__global__ __launch_bounds__(256, 2) void gemm_h(
    const __half* __restrict__ A, const __half* __restrict__ W,
    const float* __restrict__ bias,
    __half* __restrict__ Ch,
    float* __restrict__ X, __half* __restrict__ Xh,
    const float* __restrict__ gamma, const float* __restrict__ beta,
    int N, int K, int mode)
{
    extern __shared__ __align__(16) char smem[];
    const uint32_t sbase = smem_u32(smem);
    const int tid  = threadIdx.x;
    const int wid  = tid >> 5;
    const int lane = tid & 31;
    const int wm   = wid & 1;
    const int wn   = wid >> 1;
    const size_t bm = (size_t)blockIdx.y * 128;
    const size_t bn = (size_t)blockIdx.x * 128;
    const int NT = K / BK;

    const int ch0 = tid, ch1 = tid + 256;
    const int rA0 = ch0 >> 2, cA0 = ch0 & 3;
    const int rA1 = ch1 >> 2, cA1 = ch1 & 3;

    wmma::fragment<wmma::accumulator, 16, 16, 16, float> acc[4][2];
#pragma unroll
    for (int i = 0; i < 4; i++)
#pragma unroll
        for (int j = 0; j < 2; j++) wmma::fill_fragment(acc[i][j], 0.f);

#pragma unroll
    for (int t = 0; t < NS - 1; t++) {
        if (t < NT) {
            const int kk = t * BK;
            const uint32_t sb = sbase + (t % NS) * STG_B;
            cp16(sb + (rA0 * ALD + cA0 * 8) * 2, A + (bm + rA0) * K + kk + cA0 * 8);
            cp16(sb + (rA1 * ALD + cA1 * 8) * 2, A + (bm + rA1) * K + kk + cA1 * 8);
            cp16(sb + 10240 + (rA0 * ALD + cA0 * 8) * 2, W + (bn + rA0) * K + kk + cA0 * 8);
            cp16(sb + 10240 + (rA1 * ALD + cA1 * 8) * 2, W + (bn + rA1) * K + kk + cA1 * 8);
        }
        asm volatile("cp.async.commit_group;");
    }

    for (int t = 0; t < NT; t++) {
        asm volatile("cp.async.wait_group %0;" :: "n"(NS - 2));
        __syncthreads();
        {
            const __half* As = (const __half*)(smem + (t % NS) * STG_B);
            const __half* Ws = As + 5120;
#pragma unroll
            for (int ks = 0; ks < 2; ks++) {
                wmma::fragment<wmma::matrix_a, 16, 16, 16, __half, wmma::row_major> af[4];
                wmma::fragment<wmma::matrix_b, 16, 16, 16, __half, wmma::col_major> bf[2];
#pragma unroll
                for (int i = 0; i < 4; i++)
                    wmma::load_matrix_sync(af[i], As + (wm * 64 + i * 16) * ALD + ks * 16, ALD);
#pragma unroll
                for (int j = 0; j < 2; j++)
                    wmma::load_matrix_sync(bf[j], Ws + (wn * 32 + j * 16) * ALD + ks * 16, ALD);
#pragma unroll
                for (int i = 0; i < 4; i++)
#pragma unroll
                    for (int j = 0; j < 2; j++)
                        wmma::mma_sync(acc[i][j], af[i], bf[j], acc[i][j]);
            }
        }
        __syncthreads();
        {
            const int tn = t + NS - 1;
            if (tn < NT) {
                const int kk = tn * BK;
                const uint32_t sb = sbase + (tn % NS) * STG_B;
                cp16(sb + (rA0 * ALD + cA0 * 8) * 2, A + (bm + rA0) * K + kk + cA0 * 8);
                cp16(sb + (rA1 * ALD + cA1 * 8) * 2, A + (bm + rA1) * K + kk + cA1 * 8);
                cp16(sb + 10240 + (rA0 * ALD + cA0 * 8) * 2, W + (bn + rA0) * K + kk + cA0 * 8);
                cp16(sb + 10240 + (rA1 * ALD + cA1 * 8) * 2, W + (bn + rA1) * K + kk + cA1 * 8);
            }
            asm volatile("cp.async.commit_group;");
        }
    }

    float* smf = (float*)smem;
#pragma unroll
    for (int i = 0; i < 4; i++)
#pragma unroll
        for (int j = 0; j < 2; j++)
            wmma::store_matrix_sync(smf + (wm * 64 + i * 16) * CLD + wn * 32 + j * 16,
                                    acc[i][j], CLD, wmma::mem_row_major);
    __syncthreads();

    if (mode == 2) {
        float4 gv = *(const float4*)(gamma + lane * 4);
        float4 bv = *(const float4*)(beta  + lane * 4);
        float4 bz = *(const float4*)(bias  + lane * 4);
#pragma unroll
        for (int i = 0; i < 16; i++) {
            const int row = wid * 16 + i;
            float4 v = *(float4*)(smf + row * CLD + lane * 4);
            const size_t off = (bm + row) * DD + lane * 4;
            float4 xv = *(const float4*)(X + off);
            float4 tv;
            tv.x = v.x + bz.x + xv.x; tv.y = v.y + bz.y + xv.y;
            tv.z = v.z + bz.z + xv.z; tv.w = v.w + bz.w + xv.w;
            float s  = tv.x + tv.y + tv.z + tv.w;
            float s2 = tv.x*tv.x + tv.y*tv.y + tv.z*tv.z + tv.w*tv.w;
#pragma unroll
            for (int o = 16; o > 0; o >>= 1) {
                s  += __shfl_xor_sync(0xffffffffu, s,  o);
                s2 += __shfl_xor_sync(0xffffffffu, s2, o);
            }
            float mean = s * (1.f / DD);
            float var  = s2 * (1.f / DD) - mean * mean;
            float rstd = rsqrtf(var + 1e-5f);
            float4 y;
            y.x = (tv.x - mean) * rstd * gv.x + bv.x;
            y.y = (tv.y - mean) * rstd * gv.y + bv.y;
            y.z = (tv.z - mean) * rstd * gv.z + bv.z;
            y.w = (tv.w - mean) * rstd * gv.w + bv.w;
            *(float4*)(X + off) = y;
            __half2 h0 = __floats2half2_rn(y.x, y.y);
            __half2 h1 = __floats2half2_rn(y.z, y.w);
            uint2 u;
            u.x = *reinterpret_cast<uint32_t*>(&h0);
            u.y = *reinterpret_cast<uint32_t*>(&h1);
            *(uint2*)(Xh + off) = u;
        }
    } else {
#pragma unroll
        for (int i = 0; i < 16; i++) {
            int idx = i * 256 + tid;
            int row = idx >> 5;
            int cc  = (idx & 31) * 4;
            float4 v  = *(float4*)(smf + row * CLD + cc);
            float4 bz = *(const float4*)(bias + bn + cc);
            v.x += bz.x; v.y += bz.y; v.z += bz.z; v.w += bz.w;
            if (mode == 1) {
                v.x = fmaxf(v.x, 0.f); v.y = fmaxf(v.y, 0.f);
                v.z = fmaxf(v.z, 0.f); v.w = fmaxf(v.w, 0.f);
            }
            __half2 h0 = __floats2half2_rn(v.x, v.y);
            __half2 h1 = __floats2half2_rn(v.z, v.w);
            uint2 u;
            u.x = *reinterpret_cast<uint32_t*>(&h0);
            u.y = *reinterpret_cast<uint32_t*>(&h1);
            *(uint2*)(Ch + (bm + row) * N + bn + cc) = u;
        }
    }
}

// ---------------------------------------------------------------------------
// Fast exp scaled by 2^-6 (exponent-bias trick; FFMA-only)
// ---------------------------------------------------------------------------
__device__ __forceinline__ float fast_exp_s6(float x) {
    x = fmaxf(x, -80.f);
    float t  = x * 1.4426950408889634f;
    float fn = t + 12582912.f;
    int   ni = __float_as_int(fn) - 0x4B400000;
    float r  = t - (fn - 12582912.f);
    float p  = 0.00133336f;
    p = fmaf(p, r, 0.00961813f);
    p = fmaf(p, r, 0.05550411f);
    p = fmaf(p, r, 0.24022651f);
    p = fmaf(p, r, 0.69314718f);
    p = fmaf(p, r, 1.0f);
    return p * __int_as_float((ni + 121) << 23);   // * 2^(n-6)
}

// ---------------------------------------------------------------------------
// Tensor-core attention. One block per (b,h), 256 threads / 8 warps.
// ---------------------------------------------------------------------------
#define QLD 24
#define SLD 68
#define PLD 136
#define OLD 20
#define ATT_SMEM 89088

__global__ __launch_bounds__(256, 2) void attn_tc(
    const __half* __restrict__ qkv, const float* __restrict__ mask,
    __half* __restrict__ out)
{
    extern __shared__ __align__(16) char asmem[];
    __half* Qs = (__half*)(asmem);                 // 128 x QLD
    __half* Ks = (__half*)(asmem + 6144);
    __half* Vs = (__half*)(asmem + 12288);
    float*  ms = (float*) (asmem + 18432);         // 128
    float*  rs = (float*) (asmem + 18944);         // 128
    float*  Ss = (float*) (asmem + 19456);         // 128 x SLD
    __half* Ps = (__half*)(asmem + 54272);         // 128 x PLD
    float*  Os = (float*) (asmem);                 // aliases Qs/Ks after S phase

    const int h = blockIdx.x & 7;
    const int b = blockIdx.x >> 3;
    const int tid = threadIdx.x, wid = tid >> 5;

    {
        const int row = tid >> 1, ch = tid & 1;
        const __half* base = qkv + ((size_t)b * TT + row) * (3 * DD) + h * HDIM + ch * 8;
        *(uint4*)(Qs + row * QLD + ch * 8) = *(const uint4*)(base);
        *(uint4*)(Ks + row * QLD + ch * 8) = *(const uint4*)(base + DD);
        *(uint4*)(Vs + row * QLD + ch * 8) = *(const uint4*)(base + 2 * DD);
        if (tid < TT) ms[tid] = mask[b * TT + tid];
    }
    __syncthreads();

    wmma::fragment<wmma::matrix_a, 16, 16, 16, __half, wmma::row_major> qf;
    wmma::load_matrix_sync(qf, Qs + wid * 16 * QLD, QLD);

    float sum = 0.f;
    const int er = tid >> 1;
    const int eh = tid & 1;

    for (int chunk = 0; chunk < 2; chunk++) {
#pragma unroll
        for (int j = 0; j < 4; j++) {
            wmma::fragment<wmma::matrix_b, 16, 16, 16, __half, wmma::col_major> kf;
            wmma::fragment<wmma::accumulator, 16, 16, 16, float> sf;
            wmma::load_matrix_sync(kf, Ks + (chunk * 64 + j * 16) * QLD, QLD);
            wmma::fill_fragment(sf, 0.f);
            wmma::mma_sync(sf, qf, kf, sf);
            wmma::store_matrix_sync(Ss + (wid * 16) * SLD + j * 16, sf, SLD, wmma::mem_row_major);
        }
        __syncthreads();
        {
            const float* srow = Ss + er * SLD + eh * 32;
            __half* prow = Ps + er * PLD + chunk * 64 + eh * 32;
            const float* mrow = ms + chunk * 64 + eh * 32;
#pragma unroll
            for (int c = 0; c < 32; c++) {
                float p = fast_exp_s6(fmaf(srow[c], 0.25f, mrow[c]));
                __half ph = __float2half_rn(p);
                prow[c] = ph;
                sum += __half2float(ph);
            }
        }
        __syncthreads();
    }
    sum += __shfl_xor_sync(0xffffffffu, sum, 1);
    if (!eh) rs[er] = sum;
    __syncthreads();

    {
        wmma::fragment<wmma::accumulator, 16, 16, 16, float> of;
        wmma::fill_fragment(of, 0.f);
#pragma unroll
        for (int j = 0; j < 8; j++) {
            wmma::fragment<wmma::matrix_a, 16, 16, 16, __half, wmma::row_major> pf;
            wmma::fragment<wmma::matrix_b, 16, 16, 16, __half, wmma::row_major> vf;
            wmma::load_matrix_sync(pf, Ps + (wid * 16) * PLD + j * 16, PLD);
            wmma::load_matrix_sync(vf, Vs + (j * 16) * QLD, QLD);
            wmma::mma_sync(of, pf, vf, of);
        }
        wmma::store_matrix_sync(Os + (wid * 16) * OLD, of, OLD, wmma::mem_row_major);
    }
    __syncthreads();

    {
        const int r = tid >> 1, c0 = (tid & 1) * 8;
        const float inv = 1.f / rs[r];
        const float* orow = Os + r * OLD + c0;
        uint4 u;
        uint32_t* pu = &u.x;
#pragma unroll
        for (int j = 0; j < 4; j++) {
            __half2 hv = __floats2half2_rn(orow[j * 2] * inv, orow[j * 2 + 1] * inv);
            pu[j] = *reinterpret_cast<uint32_t*>(&hv);
        }
        *(uint4*)(out + ((size_t)b * TT + r) * DD + h * HDIM + c0) = u;
    }
}

// ---------------------------------------------------------------------------
extern "C" void kernel_launch(void* const* d_in, const int* in_sizes, int n_in,
                              void* d_out, int out_size)
{
    const float* x_in      = (const float*)d_in[0];
    const float* mask      = (const float*)d_in[1];
    const float* in_proj_w = (const float*)d_in[2];
    const float* in_proj_b = (const float*)d_in[3];
    const float* out_w     = (const float*)d_in[4];
    const float* out_b     = (const float*)d_in[5];
    const float* ln1_g     = (const float*)d_in[6];
    const float* ln1_b     = (const float*)d_in[7];
    const float* ff1_w     = (const float*)d_in[8];
    const float* ff1_b     = (const float*)d_in[9];
    const float* ff2_w     = (const float*)d_in[10];
    const float* ff2_b     = (const float*)d_in[11];
    const float* ln2_g     = (const float*)d_in[12];
    const float* ln2_b     = (const float*)d_in[13];
    float* x = (float*)d_out;

    __half *wqkv, *wout, *wff1, *wff2, *xh, *qkvh, *attnh, *hh;
    cudaGetSymbolAddress((void**)&wqkv, g_wqkv);
    cudaGetSymbolAddress((void**)&wout, g_wout);
    cudaGetSymbolAddress((void**)&wff1, g_wff1);
    cudaGetSymbolAddress((void**)&wff2, g_wff2);
    cudaGetSymbolAddress((void**)&xh,   g_xh);
    cudaGetSymbolAddress((void**)&qkvh, g_qkvh);
    cudaGetSymbolAddress((void**)&attnh,g_attnh);
    cudaGetSymbolAddress((void**)&hh,   g_hh);

    cudaFuncSetAttribute(gemm_h, cudaFuncAttributeMaxDynamicSharedMemorySize, SMEM_DYN);
    cudaFuncSetAttribute(attn_tc, cudaFuncAttributeMaxDynamicSharedMemorySize, ATT_SMEM);

    cudaMemcpyAsync(x, x_in, sizeof(float) * (size_t)MM * DD,
                    cudaMemcpyDeviceToDevice);
    cvt_all<<<(N_CVT + 255) / 256, 256>>>(x_in, in_proj_w, out_w, ff1_w, ff2_w);

    for (int l = 0; l < NL; l++) {
        // qkv = x @ Wqkv^T + b   [MM, 384] fp16
        gemm_h<<<dim3(3, MM / 128), 256, SMEM_DYN>>>(
            xh, wqkv + (size_t)l * 3 * DD * DD, in_proj_b + (size_t)l * 3 * DD,
            qkvh, nullptr, nullptr, nullptr, nullptr, 3 * DD, DD, 0);
        // attention -> attnh [MM, DD] fp16 (tensor-core)
        attn_tc<<<BB * HH, 256, ATT_SMEM>>>(qkvh, mask, attnh);
        // x = LN(x + attnh @ out_w^T + out_b); xh mirror
        gemm_h<<<dim3(1, MM / 128), 256, SMEM_DYN>>>(
            attnh, wout + (size_t)l * DD * DD, out_b + (size_t)l * DD,
            nullptr, x, xh, ln1_g + (size_t)l * DD, ln1_b + (size_t)l * DD, DD, DD, 2);
        // h = relu(x @ ff1_w^T + b) -> hh [MM, FFD] fp16
        gemm_h<<<dim3(4, MM / 128), 256, SMEM_DYN>>>(
            xh, wff1 + (size_t)l * FFD * DD, ff1_b + (size_t)l * FFD,
            hh, nullptr, nullptr, nullptr, nullptr, FFD, DD, 1);
        // x = LN(x + hh @ ff2_w^T + b); xh mirror
        gemm_h<<<dim3(1, MM / 128), 256, SMEM_DYN>>>(
            hh, wff2 + (size_t)l * DD * FFD, ff2_b + (size_t)l * DD,
            nullptr, x, xh, ln2_g + (size_t)l * DD, ln2_b + (size_t)l * DD, DD, FFD, 2);
    }
}